// round 2
// baseline (speedup 1.0000x reference)
#include <cuda_runtime.h>
#include <cuda_bf16.h>
#include <stdint.h>

#define P_PTS   10000
#define NPTS    100
#define MAXB    4096

// ------------------------------ scratch ------------------------------------
__device__ float g_phi[MAXB * 300];      // foveated points (B,300)
__device__ float g_h  [MAXB * 256];      // hidden concat [phi_out | l_out]
__device__ float g_W1t[300 * 128];       // W1 transposed: [k][c]
__device__ float g_Wct[256 * 256];       // [W3|W4] transposed: [k][j]
__device__ float g_b34[256];             // b3 + b4

// ------------------------------ prep ---------------------------------------
__global__ void prep_kernel(const float* __restrict__ W1,
                            const float* __restrict__ W3,
                            const float* __restrict__ W4,
                            const float* __restrict__ b3,
                            const float* __restrict__ b4) {
    int t = blockIdx.x * 256 + threadIdx.x;
    if (t < 300 * 128) {
        int k = t / 128, c = t - k * 128;
        g_W1t[t] = W1[c * 300 + k];
    }
    if (t < 256 * 256) {
        int k = t >> 8, j = t & 255;
        g_Wct[t] = (k < 128) ? W3[j * 128 + k] : W4[j * 128 + (k - 128)];
    }
    if (t < 256) g_b34[t] = b3[t] + b4[t];
}

// ------------------------------ foveate ------------------------------------
// One CTA per batch. Sequential 1024-point chunks; ordered block prefix-sum of
// the in-box mask; early exit once 100 in-box points are collected.
__global__ void foveate_kernel(const float* __restrict__ x,
                               const float* __restrict__ lt) {
    int b = blockIdx.x;
    const float* xb = x + (size_t)b * 3 * P_PTS;
    float l0 = lt[b * 3 + 0], l1 = lt[b * 3 + 1], l2 = lt[b * 3 + 2];
    float lo0 = l0 - 0.25f, hi0 = l0 + 0.25f;
    float lo1 = l1 - 0.25f, hi1 = l1 + 0.25f;
    float lo2 = l2 - 0.25f, hi2 = l2 + 0.25f;

    __shared__ float s0[NPTS], s1[NPTS], s2[NPTS];
    __shared__ int warp_cnt[8];
    __shared__ int s_run;

    int tid = threadIdx.x, lane = tid & 31, wid = tid >> 5;
    if (tid == 0) s_run = 0;
    __syncthreads();

    for (int base = 0; base < P_PTS; base += 1024) {
        int p0 = base + tid * 4;
        float v0[4], v1[4], v2[4];
        unsigned m = 0;
        if (p0 < P_PTS) {  // P divisible by 4 -> chunks fully in or out
            float4 f0 = *(const float4*)(xb + p0);
            float4 f1 = *(const float4*)(xb + P_PTS + p0);
            float4 f2 = *(const float4*)(xb + 2 * P_PTS + p0);
            v0[0]=f0.x; v0[1]=f0.y; v0[2]=f0.z; v0[3]=f0.w;
            v1[0]=f1.x; v1[1]=f1.y; v1[2]=f1.z; v1[3]=f1.w;
            v2[0]=f2.x; v2[1]=f2.y; v2[2]=f2.z; v2[3]=f2.w;
#pragma unroll
            for (int i = 0; i < 4; i++) {
                bool in = (v0[i] >= lo0) && (v0[i] <= hi0) &&
                          (v1[i] >= lo1) && (v1[i] <= hi1) &&
                          (v2[i] >= lo2) && (v2[i] <= hi2);
                m |= ((unsigned)in) << i;
            }
        }
        int cnt = __popc(m);
        int incl = cnt;
#pragma unroll
        for (int off = 1; off < 32; off <<= 1) {
            int t = __shfl_up_sync(0xffffffffu, incl, off);
            if (lane >= off) incl += t;
        }
        if (lane == 31) warp_cnt[wid] = incl;
        __syncthreads();

        int run0 = s_run;
        int woff = 0;
#pragma unroll
        for (int w = 0; w < 8; w++) woff += (w < wid) ? warp_cnt[w] : 0;
        int r = run0 + woff + (incl - cnt);
#pragma unroll
        for (int i = 0; i < 4; i++) {
            if (m & (1u << i)) {
                if (r < NPTS) { s0[r] = v0[i]; s1[r] = v1[i]; s2[r] = v2[i]; }
                r++;
            }
        }
        __syncthreads();
        if (tid == 0) {
            int tot = 0;
#pragma unroll
            for (int w = 0; w < 8; w++) tot += warp_cnt[w];
            s_run = run0 + tot;
        }
        __syncthreads();
        if (s_run >= NPTS) break;   // uniform branch (shared value)
    }

    int n = s_run;
    for (int t = tid; t < 300; t += 256) {
        int axis = t / 100, pos = t - axis * 100;
        float v = 0.0f;
        if (n > 0) {
            int j = (n >= NPTS) ? pos : (pos % n);
            v = (axis == 0) ? s0[j] : ((axis == 1) ? s1[j] : s2[j]);
        }
        g_phi[(size_t)b * 300 + t] = v;
    }
}

// ------------------------------ hidden layer --------------------------------
// h[:, :128]  = relu(phi @ W1^T + b1)   (K=300 GEMM, BM=32, BN=128, BK=15)
// h[:, 128:]  = relu(l   @ W2^T + b2)   (K=3, computed directly)
__global__ void hidden_kernel(const float* __restrict__ lt,
                              const float* __restrict__ b1,
                              const float* __restrict__ W2,
                              const float* __restrict__ b2) {
    __shared__ __align__(16) float phi_s[32 * 304];
    __shared__ __align__(16) float Bs[15 * 128];
    __shared__ float ls[32 * 3];

    int row0 = blockIdx.x * 32;
    int tid = threadIdx.x, tx = tid & 31, ty = tid >> 5;

    for (int idx = tid; idx < 32 * 300; idx += 256) {
        int r = idx / 300, k = idx - r * 300;
        phi_s[r * 304 + k] = g_phi[(size_t)(row0 + r) * 300 + k];
    }
    if (tid < 96) ls[tid] = lt[row0 * 3 + tid];

    float4 bb = *(const float4*)(b1 + tx * 4);
    float acc[4][4];
#pragma unroll
    for (int i = 0; i < 4; i++) {
        acc[i][0] = bb.x; acc[i][1] = bb.y; acc[i][2] = bb.z; acc[i][3] = bb.w;
    }
    __syncthreads();

    for (int k0 = 0; k0 < 300; k0 += 15) {
        for (int idx = tid; idx < 15 * 128; idx += 256)
            Bs[idx] = g_W1t[k0 * 128 + idx];
        __syncthreads();
#pragma unroll
        for (int kk = 0; kk < 15; kk++) {
            float4 bv = *(const float4*)&Bs[kk * 128 + tx * 4];
            float a[4];
#pragma unroll
            for (int i = 0; i < 4; i++) a[i] = phi_s[(ty * 4 + i) * 304 + k0 + kk];
#pragma unroll
            for (int i = 0; i < 4; i++) {
                acc[i][0] += a[i] * bv.x; acc[i][1] += a[i] * bv.y;
                acc[i][2] += a[i] * bv.z; acc[i][3] += a[i] * bv.w;
            }
        }
        __syncthreads();
    }

#pragma unroll
    for (int i = 0; i < 4; i++) {
        int r = row0 + ty * 4 + i;
        float4 o;
        o.x = fmaxf(acc[i][0], 0.f); o.y = fmaxf(acc[i][1], 0.f);
        o.z = fmaxf(acc[i][2], 0.f); o.w = fmaxf(acc[i][3], 0.f);
        *(float4*)&g_h[(size_t)r * 256 + tx * 4] = o;
    }

    float4 b2v = *(const float4*)(b2 + tx * 4);
    const float* b2p = (const float*)&b2v;
#pragma unroll
    for (int i = 0; i < 4; i++) {
        int rl = ty * 4 + i;
        float e0 = ls[rl * 3 + 0], e1 = ls[rl * 3 + 1], e2 = ls[rl * 3 + 2];
        float4 o;
        float ov[4];
#pragma unroll
        for (int j = 0; j < 4; j++) {
            int c = tx * 4 + j;
            float v = b2p[j] + e0 * W2[c * 3 + 0] + e1 * W2[c * 3 + 1] + e2 * W2[c * 3 + 2];
            ov[j] = fmaxf(v, 0.f);
        }
        o.x = ov[0]; o.y = ov[1]; o.z = ov[2]; o.w = ov[3];
        *(float4*)&g_h[(size_t)(row0 + rl) * 256 + 128 + tx * 4] = o;
    }
}

// ------------------------------ output layer --------------------------------
// out = relu(h @ Wc^T + b34), K=256, BM=32, BN=128, BK=16
__global__ void out_kernel(float* __restrict__ out) {
    __shared__ __align__(16) float hs[32 * 256];
    __shared__ __align__(16) float Bs[16 * 128];

    int row0 = blockIdx.x * 32, col0 = blockIdx.y * 128;
    int tid = threadIdx.x, tx = tid & 31, ty = tid >> 5;

    for (int idx = tid; idx < 32 * 256; idx += 256)
        hs[idx] = g_h[(size_t)row0 * 256 + idx];

    float4 bb = *(const float4*)&g_b34[col0 + tx * 4];
    float acc[4][4];
#pragma unroll
    for (int i = 0; i < 4; i++) {
        acc[i][0] = bb.x; acc[i][1] = bb.y; acc[i][2] = bb.z; acc[i][3] = bb.w;
    }
    __syncthreads();

    for (int k0 = 0; k0 < 256; k0 += 16) {
        for (int idx = tid; idx < 16 * 128; idx += 256) {
            int kk = idx >> 7, c = idx & 127;
            Bs[idx] = g_Wct[(k0 + kk) * 256 + col0 + c];
        }
        __syncthreads();
#pragma unroll
        for (int kk = 0; kk < 16; kk++) {
            float4 bv = *(const float4*)&Bs[kk * 128 + tx * 4];
            float a[4];
#pragma unroll
            for (int i = 0; i < 4; i++) a[i] = hs[(ty * 4 + i) * 256 + k0 + kk];
#pragma unroll
            for (int i = 0; i < 4; i++) {
                acc[i][0] += a[i] * bv.x; acc[i][1] += a[i] * bv.y;
                acc[i][2] += a[i] * bv.z; acc[i][3] += a[i] * bv.w;
            }
        }
        __syncthreads();
    }

#pragma unroll
    for (int i = 0; i < 4; i++) {
        int r = row0 + ty * 4 + i;
        float4 o;
        o.x = fmaxf(acc[i][0], 0.f); o.y = fmaxf(acc[i][1], 0.f);
        o.z = fmaxf(acc[i][2], 0.f); o.w = fmaxf(acc[i][3], 0.f);
        *(float4*)&out[(size_t)r * 256 + col0 + tx * 4] = o;
    }
}

// ------------------------------ launch --------------------------------------
extern "C" void kernel_launch(void* const* d_in, const int* in_sizes, int n_in,
                              void* d_out, int out_size) {
    const float* x  = (const float*)d_in[0];
    const float* lt = (const float*)d_in[1];
    const float* W1 = (const float*)d_in[2];
    const float* b1 = (const float*)d_in[3];
    const float* W2 = (const float*)d_in[4];
    const float* b2 = (const float*)d_in[5];
    const float* W3 = (const float*)d_in[6];
    const float* b3 = (const float*)d_in[7];
    const float* W4 = (const float*)d_in[8];
    const float* b4 = (const float*)d_in[9];
    float* out = (float*)d_out;

    int B = in_sizes[0] / (3 * P_PTS);
    if (B > MAXB) B = MAXB;

    prep_kernel<<<256, 256>>>(W1, W3, W4, b3, b4);
    foveate_kernel<<<B, 256>>>(x, lt);
    hidden_kernel<<<B / 32, 256>>>(lt, b1, W2, b2);
    out_kernel<<<dim3(B / 32, 2), 256>>>(out);
}

// round 3
// speedup vs baseline: 1.0013x; 1.0013x over previous
#include <cuda_runtime.h>
#include <cuda_bf16.h>
#include <stdint.h>

#define P_PTS   10000
#define NPTS    100
#define MAXB    4096

// ------------------------------ scratch ------------------------------------
__device__ float g_phi[MAXB * 300];      // foveated points (B,300)
__device__ float g_h  [MAXB * 256];      // hidden concat [phi_out | l_out]
__device__ float g_W1t[300 * 128];       // W1 transposed: [k][c]
__device__ float g_Wct[256 * 256];       // [W3|W4] transposed: [k][j]
__device__ float g_b34[256];             // b3 + b4

// ------------------------------ prep ---------------------------------------
__global__ void prep_kernel(const float* __restrict__ W1,
                            const float* __restrict__ W3,
                            const float* __restrict__ W4,
                            const float* __restrict__ b3,
                            const float* __restrict__ b4) {
    int t = blockIdx.x * 256 + threadIdx.x;
    if (t < 300 * 128) {
        int k = t / 128, c = t - k * 128;
        g_W1t[t] = W1[c * 300 + k];
    }
    if (t < 256 * 256) {
        int k = t >> 8, j = t & 255;
        g_Wct[t] = (k < 128) ? W3[j * 128 + k] : W4[j * 128 + (k - 128)];
    }
    if (t < 256) g_b34[t] = b3[t] + b4[t];
}

// ------------------------------ foveate ------------------------------------
// One CTA per batch. Sequential 1024-point chunks; ordered block prefix-sum of
// the in-box mask; early exit once 100 in-box points are collected.
__global__ void foveate_kernel(const float* __restrict__ x,
                               const float* __restrict__ lt) {
    int b = blockIdx.x;
    const float* xb = x + (size_t)b * 3 * P_PTS;
    float l0 = lt[b * 3 + 0], l1 = lt[b * 3 + 1], l2 = lt[b * 3 + 2];
    float lo0 = l0 - 0.25f, hi0 = l0 + 0.25f;
    float lo1 = l1 - 0.25f, hi1 = l1 + 0.25f;
    float lo2 = l2 - 0.25f, hi2 = l2 + 0.25f;

    __shared__ float s0[NPTS], s1[NPTS], s2[NPTS];
    __shared__ int warp_cnt[8];
    __shared__ int s_run;

    int tid = threadIdx.x, lane = tid & 31, wid = tid >> 5;
    if (tid == 0) s_run = 0;
    __syncthreads();

    for (int base = 0; base < P_PTS; base += 1024) {
        int p0 = base + tid * 4;
        float v0[4], v1[4], v2[4];
        unsigned m = 0;
        if (p0 < P_PTS) {  // P divisible by 4 -> chunks fully in or out
            float4 f0 = *(const float4*)(xb + p0);
            float4 f1 = *(const float4*)(xb + P_PTS + p0);
            float4 f2 = *(const float4*)(xb + 2 * P_PTS + p0);
            v0[0]=f0.x; v0[1]=f0.y; v0[2]=f0.z; v0[3]=f0.w;
            v1[0]=f1.x; v1[1]=f1.y; v1[2]=f1.z; v1[3]=f1.w;
            v2[0]=f2.x; v2[1]=f2.y; v2[2]=f2.z; v2[3]=f2.w;
#pragma unroll
            for (int i = 0; i < 4; i++) {
                bool in = (v0[i] >= lo0) && (v0[i] <= hi0) &&
                          (v1[i] >= lo1) && (v1[i] <= hi1) &&
                          (v2[i] >= lo2) && (v2[i] <= hi2);
                m |= ((unsigned)in) << i;
            }
        }
        int cnt = __popc(m);
        int incl = cnt;
#pragma unroll
        for (int off = 1; off < 32; off <<= 1) {
            int t = __shfl_up_sync(0xffffffffu, incl, off);
            if (lane >= off) incl += t;
        }
        if (lane == 31) warp_cnt[wid] = incl;
        __syncthreads();

        int run0 = s_run;
        int woff = 0;
#pragma unroll
        for (int w = 0; w < 8; w++) woff += (w < wid) ? warp_cnt[w] : 0;
        int r = run0 + woff + (incl - cnt);
#pragma unroll
        for (int i = 0; i < 4; i++) {
            if (m & (1u << i)) {
                if (r < NPTS) { s0[r] = v0[i]; s1[r] = v1[i]; s2[r] = v2[i]; }
                r++;
            }
        }
        __syncthreads();
        if (tid == 0) {
            int tot = 0;
#pragma unroll
            for (int w = 0; w < 8; w++) tot += warp_cnt[w];
            s_run = run0 + tot;
        }
        __syncthreads();
        if (s_run >= NPTS) break;   // uniform branch (shared value)
    }

    int n = s_run;
    for (int t = tid; t < 300; t += 256) {
        int axis = t / 100, pos = t - axis * 100;
        float v = 0.0f;
        if (n > 0) {
            int j = (n >= NPTS) ? pos : (pos % n);
            v = (axis == 0) ? s0[j] : ((axis == 1) ? s1[j] : s2[j]);
        }
        g_phi[(size_t)b * 300 + t] = v;
    }
}

// ------------------------------ hidden layer --------------------------------
// h[:, :128]  = relu(phi @ W1^T + b1)   (K=300 GEMM, BM=32, BN=128, BK=15)
// h[:, 128:]  = relu(l   @ W2^T + b2)   (K=3, computed directly)
__global__ void hidden_kernel(const float* __restrict__ lt,
                              const float* __restrict__ b1,
                              const float* __restrict__ W2,
                              const float* __restrict__ b2) {
    __shared__ __align__(16) float phi_s[32 * 304];
    __shared__ __align__(16) float Bs[15 * 128];
    __shared__ float ls[32 * 3];

    int row0 = blockIdx.x * 32;
    int tid = threadIdx.x, tx = tid & 31, ty = tid >> 5;

    for (int idx = tid; idx < 32 * 300; idx += 256) {
        int r = idx / 300, k = idx - r * 300;
        phi_s[r * 304 + k] = g_phi[(size_t)(row0 + r) * 300 + k];
    }
    if (tid < 96) ls[tid] = lt[row0 * 3 + tid];

    float4 bb = *(const float4*)(b1 + tx * 4);
    float acc[4][4];
#pragma unroll
    for (int i = 0; i < 4; i++) {
        acc[i][0] = bb.x; acc[i][1] = bb.y; acc[i][2] = bb.z; acc[i][3] = bb.w;
    }
    __syncthreads();

    for (int k0 = 0; k0 < 300; k0 += 15) {
        for (int idx = tid; idx < 15 * 128; idx += 256)
            Bs[idx] = g_W1t[k0 * 128 + idx];
        __syncthreads();
#pragma unroll
        for (int kk = 0; kk < 15; kk++) {
            float4 bv = *(const float4*)&Bs[kk * 128 + tx * 4];
            float a[4];
#pragma unroll
            for (int i = 0; i < 4; i++) a[i] = phi_s[(ty * 4 + i) * 304 + k0 + kk];
#pragma unroll
            for (int i = 0; i < 4; i++) {
                acc[i][0] += a[i] * bv.x; acc[i][1] += a[i] * bv.y;
                acc[i][2] += a[i] * bv.z; acc[i][3] += a[i] * bv.w;
            }
        }
        __syncthreads();
    }

#pragma unroll
    for (int i = 0; i < 4; i++) {
        int r = row0 + ty * 4 + i;
        float4 o;
        o.x = fmaxf(acc[i][0], 0.f); o.y = fmaxf(acc[i][1], 0.f);
        o.z = fmaxf(acc[i][2], 0.f); o.w = fmaxf(acc[i][3], 0.f);
        *(float4*)&g_h[(size_t)r * 256 + tx * 4] = o;
    }

    float4 b2v = *(const float4*)(b2 + tx * 4);
    const float* b2p = (const float*)&b2v;
#pragma unroll
    for (int i = 0; i < 4; i++) {
        int rl = ty * 4 + i;
        float e0 = ls[rl * 3 + 0], e1 = ls[rl * 3 + 1], e2 = ls[rl * 3 + 2];
        float4 o;
        float ov[4];
#pragma unroll
        for (int j = 0; j < 4; j++) {
            int c = tx * 4 + j;
            float v = b2p[j] + e0 * W2[c * 3 + 0] + e1 * W2[c * 3 + 1] + e2 * W2[c * 3 + 2];
            ov[j] = fmaxf(v, 0.f);
        }
        o.x = ov[0]; o.y = ov[1]; o.z = ov[2]; o.w = ov[3];
        *(float4*)&g_h[(size_t)(row0 + rl) * 256 + 128 + tx * 4] = o;
    }
}

// ------------------------------ output layer --------------------------------
// out = relu(h @ Wc^T + b34), K=256, BM=32, BN=128, BK=16
__global__ void out_kernel(float* __restrict__ out) {
    __shared__ __align__(16) float hs[32 * 256];
    __shared__ __align__(16) float Bs[16 * 128];

    int row0 = blockIdx.x * 32, col0 = blockIdx.y * 128;
    int tid = threadIdx.x, tx = tid & 31, ty = tid >> 5;

    for (int idx = tid; idx < 32 * 256; idx += 256)
        hs[idx] = g_h[(size_t)row0 * 256 + idx];

    float4 bb = *(const float4*)&g_b34[col0 + tx * 4];
    float acc[4][4];
#pragma unroll
    for (int i = 0; i < 4; i++) {
        acc[i][0] = bb.x; acc[i][1] = bb.y; acc[i][2] = bb.z; acc[i][3] = bb.w;
    }
    __syncthreads();

    for (int k0 = 0; k0 < 256; k0 += 16) {
        for (int idx = tid; idx < 16 * 128; idx += 256) {
            int kk = idx >> 7, c = idx & 127;
            Bs[idx] = g_Wct[(k0 + kk) * 256 + col0 + c];
        }
        __syncthreads();
#pragma unroll
        for (int kk = 0; kk < 16; kk++) {
            float4 bv = *(const float4*)&Bs[kk * 128 + tx * 4];
            float a[4];
#pragma unroll
            for (int i = 0; i < 4; i++) a[i] = hs[(ty * 4 + i) * 256 + k0 + kk];
#pragma unroll
            for (int i = 0; i < 4; i++) {
                acc[i][0] += a[i] * bv.x; acc[i][1] += a[i] * bv.y;
                acc[i][2] += a[i] * bv.z; acc[i][3] += a[i] * bv.w;
            }
        }
        __syncthreads();
    }

#pragma unroll
    for (int i = 0; i < 4; i++) {
        int r = row0 + ty * 4 + i;
        float4 o;
        o.x = fmaxf(acc[i][0], 0.f); o.y = fmaxf(acc[i][1], 0.f);
        o.z = fmaxf(acc[i][2], 0.f); o.w = fmaxf(acc[i][3], 0.f);
        *(float4*)&out[(size_t)r * 256 + col0 + tx * 4] = o;
    }
}

// ------------------------------ launch --------------------------------------
extern "C" void kernel_launch(void* const* d_in, const int* in_sizes, int n_in,
                              void* d_out, int out_size) {
    const float* x  = (const float*)d_in[0];
    const float* lt = (const float*)d_in[1];
    const float* W1 = (const float*)d_in[2];
    const float* b1 = (const float*)d_in[3];
    const float* W2 = (const float*)d_in[4];
    const float* b2 = (const float*)d_in[5];
    const float* W3 = (const float*)d_in[6];
    const float* b3 = (const float*)d_in[7];
    const float* W4 = (const float*)d_in[8];
    const float* b4 = (const float*)d_in[9];
    float* out = (float*)d_out;

    int B = in_sizes[0] / (3 * P_PTS);
    if (B > MAXB) B = MAXB;

    prep_kernel<<<256, 256>>>(W1, W3, W4, b3, b4);
    foveate_kernel<<<B, 256>>>(x, lt);
    hidden_kernel<<<B / 32, 256>>>(lt, b1, W2, b2);
    out_kernel<<<dim3(B / 32, 2), 256>>>(out);
}